// round 14
// baseline (speedup 1.0000x reference)
#include <cuda_runtime.h>
#include <cuda_bf16.h>
#include <cstdint>

#define HH 128
#define NPAD 100096          // = 782*128
#define EMAX 1600000
#define NTH 256
#define SCAN_B 512

// ---------------- scratch ----------------
__device__ float g_xp [NPAD * HH];          // fp32 xp (gagg gathers from this)
__device__ uint2 g_xpS [NPAD * 64];         // split xp   (combine A, 2nd half)
__device__ uint2 g_accS[NPAD * 64];         // split mean (combine A, 1st half)
__device__ uint2 g_hS  [NPAD * 64];         // split h    (proj / edgemlp A)
__device__ float g_xp0[NPAD * 2];
__device__ int   g_deg [NPAD];
__device__ int   g_off [NPAD + 1];
__device__ int   g_cur [NPAD];
__device__ int   g_srcs[EMAX];
__device__ int   g_bsum [4096];
__device__ int   g_bsumx[4096];
__device__ uint2 g_wimg[65536];             // pre-split weight images (512KB)

__device__ __forceinline__ float warp_sum(float v) {
#pragma unroll
    for (int o = 16; o > 0; o >>= 1) v += __shfl_xor_sync(0xffffffffu, v, o);
    return v;
}
__device__ __forceinline__ float quad_sum(float v) {
    v += __shfl_xor_sync(0xffffffffu, v, 1);
    v += __shfl_xor_sync(0xffffffffu, v, 2);
    return v;
}
// pack two floats' bf16-hi into one u32 (low=a, high=b); lo parts in 'lo'
__device__ __forceinline__ uint32_t pack_hilo(float a, float b, uint32_t& lo) {
    __nv_bfloat16 ha = __float2bfloat16(a), hb = __float2bfloat16(b);
    float ra = a - __bfloat162float(ha), rb = b - __bfloat162float(hb);
    __nv_bfloat16 la = __float2bfloat16(ra), lb = __float2bfloat16(rb);
    lo = (uint32_t)__bfloat16_as_ushort(la) | ((uint32_t)__bfloat16_as_ushort(lb) << 16);
    return (uint32_t)__bfloat16_as_ushort(ha) | ((uint32_t)__bfloat16_as_ushort(hb) << 16);
}
__device__ __forceinline__ uint2 pack2(float a, float b) {
    uint2 e; uint32_t lo;
    e.x = pack_hilo(a, b, lo); e.y = lo;
    return e;
}
__device__ __forceinline__ void cp16(void* dst, const void* src) {
    uint32_t d = (uint32_t)__cvta_generic_to_shared(dst);
    asm volatile("cp.async.ca.shared.global [%0], [%1], 16;" :: "r"(d), "l"(src));
}
#define CP_COMMIT() asm volatile("cp.async.commit_group;")
#define CP_WAIT0()  asm volatile("cp.async.wait_group 0;" ::: "memory")

#define MMA_BF16(d, a, b0v, b1v)                                                 \
    asm volatile(                                                                \
        "mma.sync.aligned.m16n8k16.row.col.f32.bf16.bf16.f32 "                   \
        "{%0,%1,%2,%3}, {%4,%5,%6,%7}, {%8,%9}, {%0,%1,%2,%3};"                  \
        : "+f"(d[0]), "+f"(d[1]), "+f"(d[2]), "+f"(d[3])                         \
        : "r"((a)[0]), "r"((a)[1]), "r"((a)[2]), "r"((a)[3]), "r"(b0v), "r"(b1v))

// ================= weight prep: split into [k2][n] uint2 image =================
__global__ void k_prepw(const float* __restrict__ W, uint2* __restrict__ dst, int k2max) {
    int i = blockIdx.x * blockDim.x + threadIdx.x;   // i = k2*128 + n
    if (i >= k2max * 128) return;
    int k2 = i >> 7, n = i & 127;
    dst[i] = pack2(W[(size_t)(2 * k2) * HH + n], W[(size_t)(2 * k2 + 1) * HH + n]);
}

// ================= CSR build =================
__global__ void k_hist(const int* __restrict__ ei, int E) {
    int e = blockIdx.x * blockDim.x + threadIdx.x;
    if (e >= E) return;
    atomicAdd(&g_deg[ei[E + e]], 1);
}
__global__ void __launch_bounds__(SCAN_B) k_scan1(int n) {
    __shared__ int sm[SCAN_B];
    int t = threadIdx.x;
    int idx = blockIdx.x * SCAN_B + t;
    int v = (idx < n) ? g_deg[idx] : 0;
    sm[t] = v;
    __syncthreads();
#pragma unroll
    for (int off = 1; off < SCAN_B; off <<= 1) {
        int add = (t >= off) ? sm[t - off] : 0;
        __syncthreads();
        sm[t] += add;
        __syncthreads();
    }
    if (idx < n) g_off[idx] = sm[t] - v;
    if (t == SCAN_B - 1) g_bsum[blockIdx.x] = sm[t];
}
__global__ void __launch_bounds__(1024) k_scan2(int nb) {
    __shared__ int sm[1024];
    int t = threadIdx.x;
    int v = (t < nb) ? g_bsum[t] : 0;
    sm[t] = v;
    __syncthreads();
#pragma unroll
    for (int off = 1; off < 1024; off <<= 1) {
        int add = (t >= off) ? sm[t - off] : 0;
        __syncthreads();
        sm[t] += add;
        __syncthreads();
    }
    if (t < nb) g_bsumx[t] = sm[t] - v;
}
__global__ void k_scan3(int n, int E) {
    int idx = blockIdx.x * blockDim.x + threadIdx.x;
    if (idx == 0) g_off[n] = E;
    if (idx >= n) return;
    int o = g_off[idx] + g_bsumx[idx / SCAN_B];
    g_off[idx] = o;
    g_cur[idx] = o;
}
__global__ void k_scatter(const int* __restrict__ ei, int E) {
    int e = blockIdx.x * blockDim.x + threadIdx.x;
    if (e >= E) return;
    int s = ei[e], d = ei[E + e];
    int pos = atomicAdd(&g_cur[d], 1);
    g_srcs[pos] = s;
}

// ================= layer 0 =================
__global__ void k_l0(const float* __restrict__ x, const float* __restrict__ Wp,
                     const float* __restrict__ bp, int n) {
    int i = blockIdx.x * blockDim.x + threadIdx.x;
    if (i >= n) return;
    float x0 = x[2 * i], x1 = x[2 * i + 1];
    float a = fmaxf(fmaf(x0, Wp[0], fmaf(x1, Wp[2], bp[0])), 0.f);
    float b = fmaxf(fmaf(x0, Wp[1], fmaf(x1, Wp[3], bp[1])), 0.f);
    g_xp0[2 * i] = a;
    g_xp0[2 * i + 1] = b;
}
// fused CSR mean-gather(dim2) + combine + LN; lane owns 4 consecutive cols
__global__ void __launch_bounds__(256) k_combine0(int n, const float* __restrict__ Wl,
        const float* __restrict__ bl, const float* __restrict__ Wr,
        const float* __restrict__ lnw, const float* __restrict__ lnb) {
    int node = (blockIdx.x * 256 + threadIdx.x) >> 5;
    int lane = threadIdx.x & 31;
    if (node >= n) return;
    int beg = g_off[node], end = g_off[node + 1];
    float m0 = 0.f, m1 = 0.f;
    for (int j = beg + lane; j < end; j += 32) {
        int s = __ldg(&g_srcs[j]);
        float2 v = *(const float2*)&g_xp0[2 * s];
        m0 += v.x; m1 += v.y;
    }
    m0 = warp_sum(m0); m1 = warp_sum(m1);
    float inv = 1.f / fmaxf((float)(end - beg), 1.f);
    m0 *= inv; m1 *= inv;
    float p0 = g_xp0[2 * node], p1 = g_xp0[2 * node + 1];
    float v[4]; float s = 0.f;
#pragma unroll
    for (int k = 0; k < 4; k++) {
        int c = lane * 4 + k;
        v[k] = fmaf(m0, Wl[c], fmaf(m1, Wl[HH + c],
               fmaf(p0, Wr[c], fmaf(p1, Wr[HH + c], bl[c]))));
        s += v[k];
    }
    s = warp_sum(s);
    float mu = s * (1.f / HH);
    float q = 0.f;
#pragma unroll
    for (int k = 0; k < 4; k++) { v[k] -= mu; q += v[k] * v[k]; }
    q = warp_sum(q);
    float rstd = rsqrtf(q * (1.f / HH) + 1e-5f);
#pragma unroll
    for (int k = 0; k < 4; k++) {
        int c = lane * 4 + k;
        v[k] = v[k] * rstd * lnw[c] + lnb[c];
    }
    size_t base = (size_t)node * 64 + lane * 2;
    g_hS[base]     = pack2(v[0], v[1]);
    g_hS[base + 1] = pack2(v[2], v[3]);
}

// ================= aggregation: CSR gather-reduce, warp per node =================
__global__ void __launch_bounds__(256) k_gagg(int n) {
    int node = (blockIdx.x * 256 + threadIdx.x) >> 5;
    int lane = threadIdx.x & 31;
    if (node >= n) return;
    int beg = g_off[node], end = g_off[node + 1];
    float4 a0 = make_float4(0.f, 0.f, 0.f, 0.f);
    float4 a1 = make_float4(0.f, 0.f, 0.f, 0.f);
    int j = beg;
    for (; j + 4 <= end; j += 4) {
        int s0 = __ldg(&g_srcs[j]),     s1 = __ldg(&g_srcs[j + 1]);
        int s2 = __ldg(&g_srcs[j + 2]), s3 = __ldg(&g_srcs[j + 3]);
        float4 v0 = *(const float4*)&g_xp[(size_t)s0 * HH + lane * 4];
        float4 v1 = *(const float4*)&g_xp[(size_t)s1 * HH + lane * 4];
        float4 v2 = *(const float4*)&g_xp[(size_t)s2 * HH + lane * 4];
        float4 v3 = *(const float4*)&g_xp[(size_t)s3 * HH + lane * 4];
        a0.x += v0.x + v1.x; a0.y += v0.y + v1.y;
        a0.z += v0.z + v1.z; a0.w += v0.w + v1.w;
        a1.x += v2.x + v3.x; a1.y += v2.y + v3.y;
        a1.z += v2.z + v3.z; a1.w += v2.w + v3.w;
    }
    for (; j < end; j++) {
        int s0 = __ldg(&g_srcs[j]);
        float4 v0 = *(const float4*)&g_xp[(size_t)s0 * HH + lane * 4];
        a0.x += v0.x; a0.y += v0.y; a0.z += v0.z; a0.w += v0.w;
    }
    float inv = 1.f / fmaxf((float)(end - beg), 1.f);
    float4 a;
    a.x = (a0.x + a1.x) * inv; a.y = (a0.y + a1.y) * inv;
    a.z = (a0.z + a1.z) * inv; a.w = (a0.w + a1.w) * inv;
    size_t base = (size_t)node * 64 + lane * 2;
    g_accS[base]     = pack2(a.x, a.y);
    g_accS[base + 1] = pack2(a.z, a.w);
}

// =================== bf16x3 MMA GEMM core, cp.async pre-split operands ===================
// CTA tile 128x128, 8 warps 4(M)x2(N), warp tile 32x64, k-stage 16.
// All operands pre-split: A rows in g_*S images (64 uint2/row),
// W in g_wimg [k2][128] uint2. Staging = 4x cp.async 16B per thread; no ALU.
// As[2][128][10] uint2 (80B row stride, 16B aligned); Ws[2][8][132] uint2.

#define GEMM_DECLS                                                            \
    const int t = threadIdx.x;                                                \
    const int warp = t >> 5, lane = t & 31;                                   \
    const int g = lane >> 2, q = lane & 3;                                    \
    const int mrow = (warp & 3) * 32;                                         \
    const int n0 = (warp >> 2) * 64;                                          \
    const int nhalf = warp >> 2;                                              \
    const int ar = t >> 1, ac4 = (t & 1) * 4;                                 \
    const int k2r = t >> 5, wn = (t & 31) * 4;                                \
    float c[2][8][4];                                                         \
    _Pragma("unroll")                                                         \
    for (int mt = 0; mt < 2; mt++)                                            \
        _Pragma("unroll")                                                     \
        for (int j = 0; j < 8; j++)                                           \
            _Pragma("unroll")                                                 \
            for (int u = 0; u < 4; u++) c[mt][j][u] = 0.f;                    \
    (void)nhalf;

// stage s: A rows [+s*8 uint2], W rows [s*8 + k2r]
#define CP_STAGE(buf, Asrc2, Wimg, s)                                         \
    {                                                                         \
        const uint2* a_ = (Asrc2) + (s) * 8 + ac4;                            \
        cp16(&As[buf][ar][ac4], a_);                                          \
        cp16(&As[buf][ar][ac4 + 2], a_ + 2);                                  \
        const uint2* w_ = (Wimg) + ((size_t)((s) * 8 + k2r)) * 128 + wn;      \
        cp16(&Ws[buf][k2r][wn], w_);                                          \
        cp16(&Ws[buf][k2r][wn + 2], w_ + 2);                                  \
        CP_COMMIT();                                                          \
    }

#define GEMM_COMPUTE(cur)                                                     \
    {                                                                         \
        uint32_t ah[2][4], al[2][4];                                          \
        _Pragma("unroll")                                                     \
        for (int mt = 0; mt < 2; mt++) {                                      \
            int r = mrow + mt * 16;                                           \
            uint2 x0 = As[cur][r + g][q];                                     \
            uint2 x1 = As[cur][r + g + 8][q];                                 \
            uint2 x2 = As[cur][r + g][q + 4];                                 \
            uint2 x3 = As[cur][r + g + 8][q + 4];                             \
            ah[mt][0] = x0.x; al[mt][0] = x0.y;                               \
            ah[mt][1] = x1.x; al[mt][1] = x1.y;                               \
            ah[mt][2] = x2.x; al[mt][2] = x2.y;                               \
            ah[mt][3] = x3.x; al[mt][3] = x3.y;                               \
        }                                                                     \
        _Pragma("unroll")                                                     \
        for (int j = 0; j < 8; j++) {                                         \
            int nn = n0 + 8 * j + g;                                          \
            uint2 b0 = Ws[cur][q][nn];                                        \
            uint2 b1 = Ws[cur][q + 4][nn];                                    \
            MMA_BF16(c[0][j], ah[0], b0.y, b1.y);                             \
            MMA_BF16(c[0][j], al[0], b0.x, b1.x);                             \
            MMA_BF16(c[0][j], ah[0], b0.x, b1.x);                             \
            MMA_BF16(c[1][j], ah[1], b0.y, b1.y);                             \
            MMA_BF16(c[1][j], al[1], b0.x, b1.x);                             \
            MMA_BF16(c[1][j], ah[1], b0.x, b1.x);                             \
        }                                                                     \
    }

// ---------------- proj GEMM: xp = relu(hS @ Wp + bp), K=128 ----------------
__global__ void __launch_bounds__(NTH, 2) k_proj(const uint2* __restrict__ wimg,
                                                 const float* __restrict__ bias) {
    __shared__ uint2 As[2][128][10];
    __shared__ uint2 Ws[2][8][132];
    GEMM_DECLS
    const int row0 = blockIdx.x * 128;
    const uint2* Arow = &g_hS[(size_t)(row0 + ar) * 64];

    CP_STAGE(0, Arow, wimg, 0)
    const int NT = 8;  // K=128 / 16
#pragma unroll 2
    for (int it = 0; it < NT; it++) {
        int cur = it & 1;
        CP_WAIT0();
        __syncthreads();
        if (it + 1 < NT) CP_STAGE(cur ^ 1, Arow, wimg, it + 1)
        GEMM_COMPUTE(cur)
    }

#pragma unroll
    for (int mt = 0; mt < 2; mt++) {
        int r0 = row0 + mrow + mt * 16 + g, r1 = r0 + 8;
#pragma unroll
        for (int j = 0; j < 8; j++) {
            int jc = n0 + 8 * j + 2 * q;
            float2 bv = *(const float2*)&bias[jc];
            float o00 = fmaxf(c[mt][j][0] + bv.x, 0.f);
            float o01 = fmaxf(c[mt][j][1] + bv.y, 0.f);
            float o10 = fmaxf(c[mt][j][2] + bv.x, 0.f);
            float o11 = fmaxf(c[mt][j][3] + bv.y, 0.f);
            *(float2*)&g_xp[(size_t)r0 * HH + jc] = make_float2(o00, o01);
            *(float2*)&g_xp[(size_t)r1 * HH + jc] = make_float2(o10, o11);
            g_xpS[(size_t)r0 * 64 + (jc >> 1)] = pack2(o00, o01);
            g_xpS[(size_t)r1 * 64 + (jc >> 1)] = pack2(o10, o11);
        }
    }
}

// ---------------- combine GEMM (K=256: accS | xpS) + fused LN ----------------
__global__ void __launch_bounds__(NTH, 2) k_combine(const uint2* __restrict__ wimg,
        const float* __restrict__ bl,
        const float* __restrict__ lnw, const float* __restrict__ lnb) {
    __shared__ uint2 As[2][128][10];
    __shared__ uint2 Ws[2][8][132];
    __shared__ float pbuf[128][2];
    __shared__ float vbuf[128][2];
    GEMM_DECLS
    const int row0 = blockIdx.x * 128;
    const uint2* Aa = &g_accS[(size_t)(row0 + ar) * 64];
    const uint2* Ax = &g_xpS[(size_t)(row0 + ar) * 64];

    CP_STAGE(0, Aa, wimg, 0)
    const int NT = 16;  // K=256 / 16
#pragma unroll 2
    for (int it = 0; it < NT; it++) {
        int cur = it & 1;
        CP_WAIT0();
        __syncthreads();
        if (it + 1 < NT) {
            int nx = it + 1;
            if (nx < 8) CP_STAGE(cur ^ 1, Aa, wimg, nx)
            else        CP_STAGE(cur ^ 1, Ax - 64, wimg, nx)   // (nx-8)*8 = nx*8-64
        }
        GEMM_COMPUTE(cur)
    }

    float s[2][2];
#pragma unroll
    for (int mt = 0; mt < 2; mt++) { s[mt][0] = 0.f; s[mt][1] = 0.f; }
#pragma unroll
    for (int mt = 0; mt < 2; mt++)
#pragma unroll
        for (int j = 0; j < 8; j++) {
            int jc = n0 + 8 * j + 2 * q;
            float2 bv = *(const float2*)&bl[jc];
            c[mt][j][0] += bv.x; c[mt][j][1] += bv.y;
            c[mt][j][2] += bv.x; c[mt][j][3] += bv.y;
            s[mt][0] += c[mt][j][0] + c[mt][j][1];
            s[mt][1] += c[mt][j][2] + c[mt][j][3];
        }
#pragma unroll
    for (int mt = 0; mt < 2; mt++) { s[mt][0] = quad_sum(s[mt][0]); s[mt][1] = quad_sum(s[mt][1]); }
    __syncthreads();
    if (q == 0) {
#pragma unroll
        for (int mt = 0; mt < 2; mt++) {
            pbuf[mrow + mt * 16 + g][nhalf] = s[mt][0];
            pbuf[mrow + mt * 16 + g + 8][nhalf] = s[mt][1];
        }
    }
    __syncthreads();
    float mu[2][2], vs[2][2];
#pragma unroll
    for (int mt = 0; mt < 2; mt++) {
        int lr0 = mrow + mt * 16 + g;
        mu[mt][0] = (pbuf[lr0][0] + pbuf[lr0][1]) * (1.f / HH);
        mu[mt][1] = (pbuf[lr0 + 8][0] + pbuf[lr0 + 8][1]) * (1.f / HH);
        vs[mt][0] = 0.f; vs[mt][1] = 0.f;
    }
#pragma unroll
    for (int mt = 0; mt < 2; mt++)
#pragma unroll
        for (int j = 0; j < 8; j++) {
            c[mt][j][0] -= mu[mt][0]; c[mt][j][1] -= mu[mt][0];
            c[mt][j][2] -= mu[mt][1]; c[mt][j][3] -= mu[mt][1];
            vs[mt][0] += c[mt][j][0] * c[mt][j][0] + c[mt][j][1] * c[mt][j][1];
            vs[mt][1] += c[mt][j][2] * c[mt][j][2] + c[mt][j][3] * c[mt][j][3];
        }
#pragma unroll
    for (int mt = 0; mt < 2; mt++) { vs[mt][0] = quad_sum(vs[mt][0]); vs[mt][1] = quad_sum(vs[mt][1]); }
    if (q == 0) {
#pragma unroll
        for (int mt = 0; mt < 2; mt++) {
            vbuf[mrow + mt * 16 + g][nhalf] = vs[mt][0];
            vbuf[mrow + mt * 16 + g + 8][nhalf] = vs[mt][1];
        }
    }
    __syncthreads();
#pragma unroll
    for (int mt = 0; mt < 2; mt++) {
        int lr0 = mrow + mt * 16 + g;
        float r0std = rsqrtf((vbuf[lr0][0] + vbuf[lr0][1]) * (1.f / HH) + 1e-5f);
        float r1std = rsqrtf((vbuf[lr0 + 8][0] + vbuf[lr0 + 8][1]) * (1.f / HH) + 1e-5f);
        int gr0 = row0 + lr0, gr1 = gr0 + 8;
#pragma unroll
        for (int j = 0; j < 8; j++) {
            int jc = n0 + 8 * j + 2 * q;
            float2 lw = *(const float2*)&lnw[jc];
            float2 lb = *(const float2*)&lnb[jc];
            float o00 = c[mt][j][0] * r0std * lw.x + lb.x;
            float o01 = c[mt][j][1] * r0std * lw.y + lb.y;
            float o10 = c[mt][j][2] * r1std * lw.x + lb.x;
            float o11 = c[mt][j][3] * r1std * lw.y + lb.y;
            g_hS[(size_t)gr0 * 64 + (jc >> 1)] = pack2(o00, o01);
            g_hS[(size_t)gr1 * 64 + (jc >> 1)] = pack2(o10, o11);
        }
    }
}

// ---------------- edge MLP: gather-GEMM (K=256) + fused W2 reduction ----------------
__global__ void __launch_bounds__(NTH, 2) k_edgemlp(const uint2* __restrict__ wimg,
        const int* __restrict__ eli, int Q,
        const float* __restrict__ b1,
        const float* __restrict__ W2, const float* __restrict__ b2,
        float* __restrict__ out) {
    __shared__ uint2 As[2][128][10];
    __shared__ uint2 Ws[2][8][132];
    __shared__ float pbuf[128][2];
    __shared__ int sbase[128], dbase[128];
    GEMM_DECLS
    const int q0 = blockIdx.x * 128;

    if (t < 128) {
        int qq = q0 + t, s = 0, d = 0;
        if (qq < Q) { s = eli[qq]; d = eli[Q + qq]; }
        sbase[t] = s * 64; dbase[t] = d * 64;
    }
    __syncthreads();
    const uint2* Asrc = &g_hS[(size_t)sbase[ar]];
    const uint2* Adst = &g_hS[(size_t)dbase[ar]];

    CP_STAGE(0, Asrc, wimg, 0)
    const int NT = 16;
#pragma unroll 2
    for (int it = 0; it < NT; it++) {
        int cur = it & 1;
        CP_WAIT0();
        __syncthreads();
        if (it + 1 < NT) {
            int nx = it + 1;
            if (nx < 8) CP_STAGE(cur ^ 1, Asrc, wimg, nx)
            else        CP_STAGE(cur ^ 1, Adst - 64, wimg, nx)
        }
        GEMM_COMPUTE(cur)
    }

    float s[2][2];
#pragma unroll
    for (int mt = 0; mt < 2; mt++) { s[mt][0] = 0.f; s[mt][1] = 0.f; }
#pragma unroll
    for (int mt = 0; mt < 2; mt++)
#pragma unroll
        for (int j = 0; j < 8; j++) {
            int jc = n0 + 8 * j + 2 * q;
            float2 bv = *(const float2*)&b1[jc];
            float2 wv = *(const float2*)&W2[jc];
            s[mt][0] = fmaf(fmaxf(c[mt][j][0] + bv.x, 0.f), wv.x, s[mt][0]);
            s[mt][0] = fmaf(fmaxf(c[mt][j][1] + bv.y, 0.f), wv.y, s[mt][0]);
            s[mt][1] = fmaf(fmaxf(c[mt][j][2] + bv.x, 0.f), wv.x, s[mt][1]);
            s[mt][1] = fmaf(fmaxf(c[mt][j][3] + bv.y, 0.f), wv.y, s[mt][1]);
        }
#pragma unroll
    for (int mt = 0; mt < 2; mt++) { s[mt][0] = quad_sum(s[mt][0]); s[mt][1] = quad_sum(s[mt][1]); }
    __syncthreads();
    if (q == 0) {
#pragma unroll
        for (int mt = 0; mt < 2; mt++) {
            pbuf[mrow + mt * 16 + g][nhalf] = s[mt][0];
            pbuf[mrow + mt * 16 + g + 8][nhalf] = s[mt][1];
        }
    }
    __syncthreads();
    if (nhalf == 0 && q == 0) {
        float b2v = b2[0];
#pragma unroll
        for (int mt = 0; mt < 2; mt++) {
            int lr0 = mrow + mt * 16 + g;
            int q0g = q0 + lr0;
            if (q0g < Q)     out[q0g]     = pbuf[lr0][0] + pbuf[lr0][1] + b2v;
            if (q0g + 8 < Q) out[q0g + 8] = pbuf[lr0 + 8][0] + pbuf[lr0 + 8][1] + b2v;
        }
    }
}

// ---------------- host launch ----------------
extern "C" void kernel_launch(void* const* d_in, const int* in_sizes, int n_in,
                              void* d_out, int out_size) {
    const float* x    = (const float*)d_in[0];
    const int*   ei   = (const int*)d_in[1];
    const int*   eli  = (const int*)d_in[2];
    const float* p0Wp = (const float*)d_in[3];
    const float* p0bp = (const float*)d_in[4];
    const float* p0Wl = (const float*)d_in[5];
    const float* p0bl = (const float*)d_in[6];
    const float* p0Wr = (const float*)d_in[7];
    const float* Wp_s = (const float*)d_in[8];
    const float* bp_s = (const float*)d_in[9];
    const float* Wl_s = (const float*)d_in[10];
    const float* bl_s = (const float*)d_in[11];
    const float* Wr_s = (const float*)d_in[12];
    const float* ln_w = (const float*)d_in[13];
    const float* ln_b = (const float*)d_in[14];
    const float* eW1  = (const float*)d_in[15];
    const float* eb1  = (const float*)d_in[16];
    const float* eW2  = (const float*)d_in[17];
    const float* eb2  = (const float*)d_in[18];
    float* out = (float*)d_out;

    const int n = in_sizes[0] / 2;
    const int E = in_sizes[1] / 2;
    const int Q = in_sizes[2] / 2;

    void *degp = nullptr, *wp = nullptr;
    cudaGetSymbolAddress(&degp, g_deg);
    cudaGetSymbolAddress(&wp, g_wimg);
    uint2* wimg = (uint2*)wp;

    // ---- weight image prep ----
    // proj l:     wimg + l*8192          (64 k2-rows)
    // combine l:  wimg + 16384 + l*16384 (Wl rows 0-63, Wr rows 64-127)
    // edge W1:    wimg + 49152           (128 k2-rows)
    for (int l = 0; l < 2; l++) {
        k_prepw<<<32, 256>>>(Wp_s + (size_t)l * HH * HH, wimg + (size_t)l * 8192, 64);
        k_prepw<<<32, 256>>>(Wl_s + (size_t)l * HH * HH, wimg + 16384 + (size_t)l * 16384, 64);
        k_prepw<<<32, 256>>>(Wr_s + (size_t)l * HH * HH, wimg + 16384 + (size_t)l * 16384 + 8192, 64);
    }
    k_prepw<<<64, 256>>>(eW1, wimg + 49152, 128);

    // ---- CSR build (once) ----
    cudaMemsetAsync(degp, 0, (size_t)n * sizeof(int));
    k_hist<<<(E + 255) / 256, 256>>>(ei, E);
    const int nb = (n + SCAN_B - 1) / SCAN_B;
    k_scan1<<<nb, SCAN_B>>>(n);
    k_scan2<<<1, 1024>>>(nb);
    k_scan3<<<(n + 255) / 256, 256>>>(n, E);
    k_scatter<<<(E + 255) / 256, 256>>>(ei, E);

    // ---- layer 0 ----
    k_l0<<<(n + 255) / 256, 256>>>(x, p0Wp, p0bp, n);
    k_combine0<<<(n * 32 + 255) / 256, 256>>>(n, p0Wl, p0bl, p0Wr, ln_w, ln_b);

    // ---- layers 1..2 ----
    const int gb = (n + 127) / 128;   // 782
    const int gaggB = (n * 32 + 255) / 256;
    for (int l = 0; l < 2; l++) {
        k_proj<<<gb, NTH>>>(wimg + (size_t)l * 8192, bp_s + (size_t)l * HH);
        k_gagg<<<gaggB, 256>>>(n);
        k_combine<<<gb, NTH>>>(wimg + 16384 + (size_t)l * 16384,
                               bl_s + (size_t)l * HH,
                               ln_w + (size_t)(l + 1) * HH, ln_b + (size_t)(l + 1) * HH);
    }
    k_edgemlp<<<(Q + 127) / 128, NTH>>>(wimg + 49152, eli, Q, eb1, eW2, eb2, out);
}

// round 15
// speedup vs baseline: 1.0075x; 1.0075x over previous
#include <cuda_runtime.h>
#include <cuda_bf16.h>
#include <cstdint>

#define HH 128
#define NPAD 100096          // = 782*128
#define EMAX 1600000
#define NTH 256
#define SCAN_B 512

// ---------------- scratch ----------------
__device__ uint2 g_xpS [NPAD * 64];         // split xp  (combine A 2nd half + gagg gather)
__device__ uint2 g_accS[NPAD * 64];         // split mean (combine A 1st half)
__device__ uint2 g_hS  [NPAD * 64];         // split h    (proj / edgemlp A)
__device__ float g_xp0[NPAD * 2];
__device__ int   g_deg [NPAD];
__device__ int   g_off [NPAD + 1];
__device__ int   g_cur [NPAD];
__device__ int   g_srcs[EMAX];
__device__ int   g_bsum [4096];
__device__ int   g_bsumx[4096];
__device__ uint2 g_wimg[65536];             // pre-split weight images (512KB)

__device__ __forceinline__ float warp_sum(float v) {
#pragma unroll
    for (int o = 16; o > 0; o >>= 1) v += __shfl_xor_sync(0xffffffffu, v, o);
    return v;
}
__device__ __forceinline__ float quad_sum(float v) {
    v += __shfl_xor_sync(0xffffffffu, v, 1);
    v += __shfl_xor_sync(0xffffffffu, v, 2);
    return v;
}
// pack two floats' bf16-hi into one u32 (low=a, high=b); lo parts in 'lo'
__device__ __forceinline__ uint32_t pack_hilo(float a, float b, uint32_t& lo) {
    __nv_bfloat16 ha = __float2bfloat16(a), hb = __float2bfloat16(b);
    float ra = a - __bfloat162float(ha), rb = b - __bfloat162float(hb);
    __nv_bfloat16 la = __float2bfloat16(ra), lb = __float2bfloat16(rb);
    lo = (uint32_t)__bfloat16_as_ushort(la) | ((uint32_t)__bfloat16_as_ushort(lb) << 16);
    return (uint32_t)__bfloat16_as_ushort(ha) | ((uint32_t)__bfloat16_as_ushort(hb) << 16);
}
__device__ __forceinline__ uint2 pack2(float a, float b) {
    uint2 e; uint32_t lo;
    e.x = pack_hilo(a, b, lo); e.y = lo;
    return e;
}
// reconstruct 2 fp32 from a split uint2: f(bf16 bits b) == (b<<16) as float (exact)
__device__ __forceinline__ float2 up2(uint2 e) {
    float2 r;
    r.x = __uint_as_float(e.x << 16) + __uint_as_float(e.y << 16);
    r.y = __uint_as_float(e.x & 0xffff0000u) + __uint_as_float(e.y & 0xffff0000u);
    return r;
}
__device__ __forceinline__ void cp16(void* dst, const void* src) {
    uint32_t d = (uint32_t)__cvta_generic_to_shared(dst);
    asm volatile("cp.async.ca.shared.global [%0], [%1], 16;" :: "r"(d), "l"(src));
}
#define CP_COMMIT() asm volatile("cp.async.commit_group;")
#define CP_WAIT0()  asm volatile("cp.async.wait_group 0;" ::: "memory")

#define MMA_BF16(d, a, b0v, b1v)                                                 \
    asm volatile(                                                                \
        "mma.sync.aligned.m16n8k16.row.col.f32.bf16.bf16.f32 "                   \
        "{%0,%1,%2,%3}, {%4,%5,%6,%7}, {%8,%9}, {%0,%1,%2,%3};"                  \
        : "+f"(d[0]), "+f"(d[1]), "+f"(d[2]), "+f"(d[3])                         \
        : "r"((a)[0]), "r"((a)[1]), "r"((a)[2]), "r"((a)[3]), "r"(b0v), "r"(b1v))

// ================= fused prep: ALL weight images + g_deg zero, ONE launch =================
// wimg layout (k2-rows of 128 uint2): [0,64) Wp0 [64,128) Wp1 [128,192) Wl0
// [192,256) Wr0 [256,320) Wl1 [320,384) Wr1 [384,512) eW1
__global__ void k_prep(const float* __restrict__ Wp_s, const float* __restrict__ Wl_s,
                       const float* __restrict__ Wr_s, const float* __restrict__ eW1,
                       int n) {
    int i = blockIdx.x * blockDim.x + threadIdx.x;
    if (i < 65536) {
        int r = i >> 7, nn = i & 127;
        const float* src; int k2;
        if (r < 64)       { src = Wp_s;          k2 = r; }
        else if (r < 128) { src = Wp_s + 16384;  k2 = r - 64; }
        else if (r < 192) { src = Wl_s;          k2 = r - 128; }
        else if (r < 256) { src = Wr_s;          k2 = r - 192; }
        else if (r < 320) { src = Wl_s + 16384;  k2 = r - 256; }
        else if (r < 384) { src = Wr_s + 16384;  k2 = r - 320; }
        else              { src = eW1;           k2 = r - 384; }
        g_wimg[i] = pack2(src[(size_t)(2 * k2) * HH + nn],
                          src[(size_t)(2 * k2 + 1) * HH + nn]);
    } else {
        int j = i - 65536;
        if (j < n) g_deg[j] = 0;
    }
}

// ================= hist + layer-0 projection, fused =================
__global__ void k_hist_l0(const int* __restrict__ ei, int E,
                          const float* __restrict__ x, const float* __restrict__ Wp,
                          const float* __restrict__ bp, int n) {
    int e = blockIdx.x * blockDim.x + threadIdx.x;
    if (e < n) {
        float x0 = x[2 * e], x1 = x[2 * e + 1];
        g_xp0[2 * e]     = fmaxf(fmaf(x0, Wp[0], fmaf(x1, Wp[2], bp[0])), 0.f);
        g_xp0[2 * e + 1] = fmaxf(fmaf(x0, Wp[1], fmaf(x1, Wp[3], bp[1])), 0.f);
    }
    if (e < E) atomicAdd(&g_deg[ei[E + e]], 1);
}

// ================= CSR scans =================
__global__ void __launch_bounds__(SCAN_B) k_scan1(int n) {
    __shared__ int sm[SCAN_B];
    int t = threadIdx.x;
    int idx = blockIdx.x * SCAN_B + t;
    int v = (idx < n) ? g_deg[idx] : 0;
    sm[t] = v;
    __syncthreads();
#pragma unroll
    for (int off = 1; off < SCAN_B; off <<= 1) {
        int add = (t >= off) ? sm[t - off] : 0;
        __syncthreads();
        sm[t] += add;
        __syncthreads();
    }
    if (idx < n) g_off[idx] = sm[t] - v;
    if (t == SCAN_B - 1) g_bsum[blockIdx.x] = sm[t];
}
__global__ void __launch_bounds__(1024) k_scan2(int nb) {
    __shared__ int sm[1024];
    int t = threadIdx.x;
    int v = (t < nb) ? g_bsum[t] : 0;
    sm[t] = v;
    __syncthreads();
#pragma unroll
    for (int off = 1; off < 1024; off <<= 1) {
        int add = (t >= off) ? sm[t - off] : 0;
        __syncthreads();
        sm[t] += add;
        __syncthreads();
    }
    if (t < nb) g_bsumx[t] = sm[t] - v;
}
__global__ void k_scan3(int n, int E) {
    int idx = blockIdx.x * blockDim.x + threadIdx.x;
    if (idx == 0) g_off[n] = E;
    if (idx >= n) return;
    int o = g_off[idx] + g_bsumx[idx / SCAN_B];
    g_off[idx] = o;
    g_cur[idx] = o;
}
__global__ void k_scatter(const int* __restrict__ ei, int E) {
    int e = blockIdx.x * blockDim.x + threadIdx.x;
    if (e >= E) return;
    int s = ei[e], d = ei[E + e];
    int pos = atomicAdd(&g_cur[d], 1);
    g_srcs[pos] = s;
}

// ============ layer 0 combine: CSR mean-gather (dim2) + combine + LN ============
__global__ void __launch_bounds__(256) k_combine0(int n, const float* __restrict__ Wl,
        const float* __restrict__ bl, const float* __restrict__ Wr,
        const float* __restrict__ lnw, const float* __restrict__ lnb) {
    int node = (blockIdx.x * 256 + threadIdx.x) >> 5;
    int lane = threadIdx.x & 31;
    if (node >= n) return;
    int beg = g_off[node], end = g_off[node + 1];
    float m0 = 0.f, m1 = 0.f;
    for (int j = beg + lane; j < end; j += 32) {
        int s = __ldg(&g_srcs[j]);
        float2 v = *(const float2*)&g_xp0[2 * s];
        m0 += v.x; m1 += v.y;
    }
    m0 = warp_sum(m0); m1 = warp_sum(m1);
    float inv = 1.f / fmaxf((float)(end - beg), 1.f);
    m0 *= inv; m1 *= inv;
    float p0 = g_xp0[2 * node], p1 = g_xp0[2 * node + 1];
    float v[4]; float s = 0.f;
#pragma unroll
    for (int k = 0; k < 4; k++) {
        int c = lane * 4 + k;
        v[k] = fmaf(m0, Wl[c], fmaf(m1, Wl[HH + c],
               fmaf(p0, Wr[c], fmaf(p1, Wr[HH + c], bl[c]))));
        s += v[k];
    }
    s = warp_sum(s);
    float mu = s * (1.f / HH);
    float q = 0.f;
#pragma unroll
    for (int k = 0; k < 4; k++) { v[k] -= mu; q += v[k] * v[k]; }
    q = warp_sum(q);
    float rstd = rsqrtf(q * (1.f / HH) + 1e-5f);
#pragma unroll
    for (int k = 0; k < 4; k++) {
        int c = lane * 4 + k;
        v[k] = v[k] * rstd * lnw[c] + lnb[c];
    }
    size_t base = (size_t)node * 64 + lane * 2;
    g_hS[base]     = pack2(v[0], v[1]);
    g_hS[base + 1] = pack2(v[2], v[3]);
}

// ======= aggregation: CSR gather-reduce from split xp image, warp per node =======
__global__ void __launch_bounds__(256) k_gagg(int n) {
    int node = (blockIdx.x * 256 + threadIdx.x) >> 5;
    int lane = threadIdx.x & 31;
    if (node >= n) return;
    int beg = g_off[node], end = g_off[node + 1];
    float4 a0 = make_float4(0.f, 0.f, 0.f, 0.f);
    float4 a1 = make_float4(0.f, 0.f, 0.f, 0.f);
    int j = beg;
    for (; j + 2 <= end; j += 2) {
        int s0 = __ldg(&g_srcs[j]), s1 = __ldg(&g_srcs[j + 1]);
        uint4 p0 = *(const uint4*)&g_xpS[(size_t)s0 * 64 + lane * 2];
        uint4 p1 = *(const uint4*)&g_xpS[(size_t)s1 * 64 + lane * 2];
        float2 u;
        u = up2(make_uint2(p0.x, p0.y)); a0.x += u.x; a0.y += u.y;
        u = up2(make_uint2(p0.z, p0.w)); a0.z += u.x; a0.w += u.y;
        u = up2(make_uint2(p1.x, p1.y)); a1.x += u.x; a1.y += u.y;
        u = up2(make_uint2(p1.z, p1.w)); a1.z += u.x; a1.w += u.y;
    }
    if (j < end) {
        int s0 = __ldg(&g_srcs[j]);
        uint4 p0 = *(const uint4*)&g_xpS[(size_t)s0 * 64 + lane * 2];
        float2 u;
        u = up2(make_uint2(p0.x, p0.y)); a0.x += u.x; a0.y += u.y;
        u = up2(make_uint2(p0.z, p0.w)); a0.z += u.x; a0.w += u.y;
    }
    float inv = 1.f / fmaxf((float)(end - beg), 1.f);
    float4 a;
    a.x = (a0.x + a1.x) * inv; a.y = (a0.y + a1.y) * inv;
    a.z = (a0.z + a1.z) * inv; a.w = (a0.w + a1.w) * inv;
    size_t base = (size_t)node * 64 + lane * 2;
    g_accS[base]     = pack2(a.x, a.y);
    g_accS[base + 1] = pack2(a.z, a.w);
}

// =================== bf16x3 MMA GEMM core, cp.async pre-split operands ===================
// CTA tile 128x128, 8 warps 4(M)x2(N), warp tile 32x64, k-stage 16.
// As[2][128][10] uint2 (80B row stride, 16B aligned); Ws[2][8][132] uint2.

#define GEMM_DECLS                                                            \
    const int t = threadIdx.x;                                                \
    const int warp = t >> 5, lane = t & 31;                                   \
    const int g = lane >> 2, q = lane & 3;                                    \
    const int mrow = (warp & 3) * 32;                                         \
    const int n0 = (warp >> 2) * 64;                                          \
    const int nhalf = warp >> 2;                                              \
    const int ar = t >> 1, ac4 = (t & 1) * 4;                                 \
    const int k2r = t >> 5, wn = (t & 31) * 4;                                \
    float c[2][8][4];                                                         \
    _Pragma("unroll")                                                         \
    for (int mt = 0; mt < 2; mt++)                                            \
        _Pragma("unroll")                                                     \
        for (int j = 0; j < 8; j++)                                           \
            _Pragma("unroll")                                                 \
            for (int u = 0; u < 4; u++) c[mt][j][u] = 0.f;                    \
    (void)nhalf;

#define CP_STAGE(buf, Asrc2, Wimg, s)                                         \
    {                                                                         \
        const uint2* a_ = (Asrc2) + (s) * 8 + ac4;                            \
        cp16(&As[buf][ar][ac4], a_);                                          \
        cp16(&As[buf][ar][ac4 + 2], a_ + 2);                                  \
        const uint2* w_ = (Wimg) + ((size_t)((s) * 8 + k2r)) * 128 + wn;      \
        cp16(&Ws[buf][k2r][wn], w_);                                          \
        cp16(&Ws[buf][k2r][wn + 2], w_ + 2);                                  \
        CP_COMMIT();                                                          \
    }

#define GEMM_COMPUTE(cur)                                                     \
    {                                                                         \
        uint32_t ah[2][4], al[2][4];                                          \
        _Pragma("unroll")                                                     \
        for (int mt = 0; mt < 2; mt++) {                                      \
            int r = mrow + mt * 16;                                           \
            uint2 x0 = As[cur][r + g][q];                                     \
            uint2 x1 = As[cur][r + g + 8][q];                                 \
            uint2 x2 = As[cur][r + g][q + 4];                                 \
            uint2 x3 = As[cur][r + g + 8][q + 4];                             \
            ah[mt][0] = x0.x; al[mt][0] = x0.y;                               \
            ah[mt][1] = x1.x; al[mt][1] = x1.y;                               \
            ah[mt][2] = x2.x; al[mt][2] = x2.y;                               \
            ah[mt][3] = x3.x; al[mt][3] = x3.y;                               \
        }                                                                     \
        _Pragma("unroll")                                                     \
        for (int j = 0; j < 8; j++) {                                         \
            int nn = n0 + 8 * j + g;                                          \
            uint2 b0 = Ws[cur][q][nn];                                        \
            uint2 b1 = Ws[cur][q + 4][nn];                                    \
            MMA_BF16(c[0][j], ah[0], b0.y, b1.y);                             \
            MMA_BF16(c[0][j], al[0], b0.x, b1.x);                             \
            MMA_BF16(c[0][j], ah[0], b0.x, b1.x);                             \
            MMA_BF16(c[1][j], ah[1], b0.y, b1.y);                             \
            MMA_BF16(c[1][j], al[1], b0.x, b1.x);                             \
            MMA_BF16(c[1][j], ah[1], b0.x, b1.x);                             \
        }                                                                     \
    }

// ---------------- proj GEMM: xpS = relu(hS @ Wp + bp), K=128 ----------------
__global__ void __launch_bounds__(NTH, 2) k_proj(const uint2* __restrict__ wimg,
                                                 const float* __restrict__ bias) {
    __shared__ uint2 As[2][128][10];
    __shared__ uint2 Ws[2][8][132];
    GEMM_DECLS
    const int row0 = blockIdx.x * 128;
    const uint2* Arow = &g_hS[(size_t)(row0 + ar) * 64];

    CP_STAGE(0, Arow, wimg, 0)
    const int NT = 8;  // K=128 / 16
#pragma unroll 2
    for (int it = 0; it < NT; it++) {
        int cur = it & 1;
        CP_WAIT0();
        __syncthreads();
        if (it + 1 < NT) CP_STAGE(cur ^ 1, Arow, wimg, it + 1)
        GEMM_COMPUTE(cur)
    }

#pragma unroll
    for (int mt = 0; mt < 2; mt++) {
        int r0 = row0 + mrow + mt * 16 + g, r1 = r0 + 8;
#pragma unroll
        for (int j = 0; j < 8; j++) {
            int jc = n0 + 8 * j + 2 * q;
            float2 bv = *(const float2*)&bias[jc];
            float o00 = fmaxf(c[mt][j][0] + bv.x, 0.f);
            float o01 = fmaxf(c[mt][j][1] + bv.y, 0.f);
            float o10 = fmaxf(c[mt][j][2] + bv.x, 0.f);
            float o11 = fmaxf(c[mt][j][3] + bv.y, 0.f);
            g_xpS[(size_t)r0 * 64 + (jc >> 1)] = pack2(o00, o01);
            g_xpS[(size_t)r1 * 64 + (jc >> 1)] = pack2(o10, o11);
        }
    }
}

// ---------------- combine GEMM (K=256: accS | xpS) + fused LN ----------------
__global__ void __launch_bounds__(NTH, 2) k_combine(const uint2* __restrict__ wimg,
        const float* __restrict__ bl,
        const float* __restrict__ lnw, const float* __restrict__ lnb) {
    __shared__ uint2 As[2][128][10];
    __shared__ uint2 Ws[2][8][132];
    __shared__ float pbuf[128][2];
    __shared__ float vbuf[128][2];
    GEMM_DECLS
    const int row0 = blockIdx.x * 128;
    const uint2* Aa = &g_accS[(size_t)(row0 + ar) * 64];
    const uint2* Ax = &g_xpS[(size_t)(row0 + ar) * 64];

    CP_STAGE(0, Aa, wimg, 0)
    const int NT = 16;  // K=256 / 16
#pragma unroll 2
    for (int it = 0; it < NT; it++) {
        int cur = it & 1;
        CP_WAIT0();
        __syncthreads();
        if (it + 1 < NT) {
            int nx = it + 1;
            if (nx < 8) CP_STAGE(cur ^ 1, Aa, wimg, nx)
            else        CP_STAGE(cur ^ 1, Ax - 64, wimg, nx)   // (nx-8)*8 = nx*8-64
        }
        GEMM_COMPUTE(cur)
    }

    float s[2][2];
#pragma unroll
    for (int mt = 0; mt < 2; mt++) { s[mt][0] = 0.f; s[mt][1] = 0.f; }
#pragma unroll
    for (int mt = 0; mt < 2; mt++)
#pragma unroll
        for (int j = 0; j < 8; j++) {
            int jc = n0 + 8 * j + 2 * q;
            float2 bv = *(const float2*)&bl[jc];
            c[mt][j][0] += bv.x; c[mt][j][1] += bv.y;
            c[mt][j][2] += bv.x; c[mt][j][3] += bv.y;
            s[mt][0] += c[mt][j][0] + c[mt][j][1];
            s[mt][1] += c[mt][j][2] + c[mt][j][3];
        }
#pragma unroll
    for (int mt = 0; mt < 2; mt++) { s[mt][0] = quad_sum(s[mt][0]); s[mt][1] = quad_sum(s[mt][1]); }
    __syncthreads();
    if (q == 0) {
#pragma unroll
        for (int mt = 0; mt < 2; mt++) {
            pbuf[mrow + mt * 16 + g][nhalf] = s[mt][0];
            pbuf[mrow + mt * 16 + g + 8][nhalf] = s[mt][1];
        }
    }
    __syncthreads();
    float mu[2][2], vs[2][2];
#pragma unroll
    for (int mt = 0; mt < 2; mt++) {
        int lr0 = mrow + mt * 16 + g;
        mu[mt][0] = (pbuf[lr0][0] + pbuf[lr0][1]) * (1.f / HH);
        mu[mt][1] = (pbuf[lr0 + 8][0] + pbuf[lr0 + 8][1]) * (1.f / HH);
        vs[mt][0] = 0.f; vs[mt][1] = 0.f;
    }
#pragma unroll
    for (int mt = 0; mt < 2; mt++)
#pragma unroll
        for (int j = 0; j < 8; j++) {
            c[mt][j][0] -= mu[mt][0]; c[mt][j][1] -= mu[mt][0];
            c[mt][j][2] -= mu[mt][1]; c[mt][j][3] -= mu[mt][1];
            vs[mt][0] += c[mt][j][0] * c[mt][j][0] + c[mt][j][1] * c[mt][j][1];
            vs[mt][1] += c[mt][j][2] * c[mt][j][2] + c[mt][j][3] * c[mt][j][3];
        }
#pragma unroll
    for (int mt = 0; mt < 2; mt++) { vs[mt][0] = quad_sum(vs[mt][0]); vs[mt][1] = quad_sum(vs[mt][1]); }
    if (q == 0) {
#pragma unroll
        for (int mt = 0; mt < 2; mt++) {
            vbuf[mrow + mt * 16 + g][nhalf] = vs[mt][0];
            vbuf[mrow + mt * 16 + g + 8][nhalf] = vs[mt][1];
        }
    }
    __syncthreads();
#pragma unroll
    for (int mt = 0; mt < 2; mt++) {
        int lr0 = mrow + mt * 16 + g;
        float r0std = rsqrtf((vbuf[lr0][0] + vbuf[lr0][1]) * (1.f / HH) + 1e-5f);
        float r1std = rsqrtf((vbuf[lr0 + 8][0] + vbuf[lr0 + 8][1]) * (1.f / HH) + 1e-5f);
        int gr0 = row0 + lr0, gr1 = gr0 + 8;
#pragma unroll
        for (int j = 0; j < 8; j++) {
            int jc = n0 + 8 * j + 2 * q;
            float2 lw = *(const float2*)&lnw[jc];
            float2 lb = *(const float2*)&lnb[jc];
            float o00 = c[mt][j][0] * r0std * lw.x + lb.x;
            float o01 = c[mt][j][1] * r0std * lw.y + lb.y;
            float o10 = c[mt][j][2] * r1std * lw.x + lb.x;
            float o11 = c[mt][j][3] * r1std * lw.y + lb.y;
            g_hS[(size_t)gr0 * 64 + (jc >> 1)] = pack2(o00, o01);
            g_hS[(size_t)gr1 * 64 + (jc >> 1)] = pack2(o10, o11);
        }
    }
}

// ---------------- edge MLP: gather-GEMM (K=256) + fused W2 reduction ----------------
__global__ void __launch_bounds__(NTH, 2) k_edgemlp(const uint2* __restrict__ wimg,
        const int* __restrict__ eli, int Q,
        const float* __restrict__ b1,
        const float* __restrict__ W2, const float* __restrict__ b2,
        float* __restrict__ out) {
    __shared__ uint2 As[2][128][10];
    __shared__ uint2 Ws[2][8][132];
    __shared__ float pbuf[128][2];
    __shared__ int sbase[128], dbase[128];
    GEMM_DECLS
    const int q0 = blockIdx.x * 128;

    if (t < 128) {
        int qq = q0 + t, s = 0, d = 0;
        if (qq < Q) { s = eli[qq]; d = eli[Q + qq]; }
        sbase[t] = s * 64; dbase[t] = d * 64;
    }
    __syncthreads();
    const uint2* Asrc = &g_hS[(size_t)sbase[ar]];
    const uint2* Adst = &g_hS[(size_t)dbase[ar]];

    CP_STAGE(0, Asrc, wimg, 0)
    const int NT = 16;
#pragma unroll 2
    for (int it = 0; it < NT; it++) {
        int cur = it & 1;
        CP_WAIT0();
        __syncthreads();
        if (it + 1 < NT) {
            int nx = it + 1;
            if (nx < 8) CP_STAGE(cur ^ 1, Asrc, wimg, nx)
            else        CP_STAGE(cur ^ 1, Adst - 64, wimg, nx)
        }
        GEMM_COMPUTE(cur)
    }

    float s[2][2];
#pragma unroll
    for (int mt = 0; mt < 2; mt++) { s[mt][0] = 0.f; s[mt][1] = 0.f; }
#pragma unroll
    for (int mt = 0; mt < 2; mt++)
#pragma unroll
        for (int j = 0; j < 8; j++) {
            int jc = n0 + 8 * j + 2 * q;
            float2 bv = *(const float2*)&b1[jc];
            float2 wv = *(const float2*)&W2[jc];
            s[mt][0] = fmaf(fmaxf(c[mt][j][0] + bv.x, 0.f), wv.x, s[mt][0]);
            s[mt][0] = fmaf(fmaxf(c[mt][j][1] + bv.y, 0.f), wv.y, s[mt][0]);
            s[mt][1] = fmaf(fmaxf(c[mt][j][2] + bv.x, 0.f), wv.x, s[mt][1]);
            s[mt][1] = fmaf(fmaxf(c[mt][j][3] + bv.y, 0.f), wv.y, s[mt][1]);
        }
#pragma unroll
    for (int mt = 0; mt < 2; mt++) { s[mt][0] = quad_sum(s[mt][0]); s[mt][1] = quad_sum(s[mt][1]); }
    __syncthreads();
    if (q == 0) {
#pragma unroll
        for (int mt = 0; mt < 2; mt++) {
            pbuf[mrow + mt * 16 + g][nhalf] = s[mt][0];
            pbuf[mrow + mt * 16 + g + 8][nhalf] = s[mt][1];
        }
    }
    __syncthreads();
    if (nhalf == 0 && q == 0) {
        float b2v = b2[0];
#pragma unroll
        for (int mt = 0; mt < 2; mt++) {
            int lr0 = mrow + mt * 16 + g;
            int q0g = q0 + lr0;
            if (q0g < Q)     out[q0g]     = pbuf[lr0][0] + pbuf[lr0][1] + b2v;
            if (q0g + 8 < Q) out[q0g + 8] = pbuf[lr0 + 8][0] + pbuf[lr0 + 8][1] + b2v;
        }
    }
}

// ---------------- host launch ----------------
extern "C" void kernel_launch(void* const* d_in, const int* in_sizes, int n_in,
                              void* d_out, int out_size) {
    const float* x    = (const float*)d_in[0];
    const int*   ei   = (const int*)d_in[1];
    const int*   eli  = (const int*)d_in[2];
    const float* p0Wp = (const float*)d_in[3];
    const float* p0bp = (const float*)d_in[4];
    const float* p0Wl = (const float*)d_in[5];
    const float* p0bl = (const float*)d_in[6];
    const float* p0Wr = (const float*)d_in[7];
    const float* Wp_s = (const float*)d_in[8];
    const float* bp_s = (const float*)d_in[9];
    const float* Wl_s = (const float*)d_in[10];
    const float* bl_s = (const float*)d_in[11];
    const float* Wr_s = (const float*)d_in[12];
    const float* ln_w = (const float*)d_in[13];
    const float* ln_b = (const float*)d_in[14];
    const float* eW1  = (const float*)d_in[15];
    const float* eb1  = (const float*)d_in[16];
    const float* eW2  = (const float*)d_in[17];
    const float* eb2  = (const float*)d_in[18];
    float* out = (float*)d_out;

    const int n = in_sizes[0] / 2;
    const int E = in_sizes[1] / 2;
    const int Q = in_sizes[2] / 2;

    void* wp = nullptr;
    cudaGetSymbolAddress(&wp, g_wimg);
    uint2* wimg = (uint2*)wp;

    // prep (all weight images + deg zeroing, one launch)
    k_prep<<<(65536 + n + 255) / 256, 256>>>(Wp_s, Wl_s, Wr_s, eW1, n);
    // hist + layer-0 projection (fused)
    k_hist_l0<<<(E + 255) / 256, 256>>>(ei, E, x, p0Wp, p0bp, n);
    const int nb = (n + SCAN_B - 1) / SCAN_B;
    k_scan1<<<nb, SCAN_B>>>(n);
    k_scan2<<<1, 1024>>>(nb);
    k_scan3<<<(n + 255) / 256, 256>>>(n, E);
    k_scatter<<<(E + 255) / 256, 256>>>(ei, E);

    k_combine0<<<(n * 32 + 255) / 256, 256>>>(n, p0Wl, p0bl, p0Wr, ln_w, ln_b);

    const int gb = (n + 127) / 128;   // 782
    const int gaggB = (n * 32 + 255) / 256;
    for (int l = 0; l < 2; l++) {
        k_proj<<<gb, NTH>>>(wimg + (size_t)l * 8192, bp_s + (size_t)l * HH);
        k_gagg<<<gaggB, 256>>>(n);
        k_combine<<<gb, NTH>>>(wimg + 16384 + (size_t)l * 16384,
                               bl_s + (size_t)l * HH,
                               ln_w + (size_t)(l + 1) * HH, ln_b + (size_t)(l + 1) * HH);
    }
    k_edgemlp<<<(Q + 127) / 128, NTH>>>(wimg + 49152, eli, Q, eb1, eW2, eb2, out);
}